// round 4
// baseline (speedup 1.0000x reference)
#include <cuda_runtime.h>
#include <cstdint>

// Problem constants
#define NB      1024      // batch
#define SEQT    512       // seq_len
#define UNITS_  256
#define NCHARS  128
#define ZC      1024      // 4*UNITS

// Tiling
#define BM      64        // batch rows per block
#define HN      32        // hidden units per block
#define BC      128       // z columns per block = 4*HN (i,f,g,o groups of 32)
#define NBT     16        // batch tiles
#define NHT     8         // hidden tiles
#define NBLK    128       // NBT*NHT  (<= 148 SMs, single wave, 1 CTA/SM)
#define NTHR    256

// Shared memory layout (bytes)
#define W_S_ELEMS   (256*128)          // Wh slice, [k][c] layout
#define H_S_ELEMS   (64*256)           // h tile, [row][k] layout (z tile overlays)
#define SMEM_W_OFF    0
#define SMEM_H_OFF    (W_S_ELEMS*4)                    // 131072
#define SMEM_BIAS_OFF (SMEM_H_OFF + H_S_ELEMS*4)       // 196608
#define SMEM_HROW_OFF (SMEM_BIAS_OFF + 512)            // 197120 (final stage, 8x256 floats)
#define SMEM_TOTAL    (SMEM_HROW_OFF + 8*256*4)        // 205312 bytes

// Device-global scratch (allowed; zero-initialized at module load)
__device__ float g_h[2][NB * UNITS_];
__device__ unsigned int g_count;
__device__ unsigned int g_gen;

__device__ __forceinline__ float fast_sigmoid(float x) {
    return __fdividef(1.0f, 1.0f + __expf(-x));   // saturates correctly at +-inf
}
__device__ __forceinline__ float fast_tanh(float x) {
    float e = __expf(2.0f * x);
    return 1.0f - __fdividef(2.0f, e + 1.0f);      // no NaN at large |x|
}

// Sense-reversing grid barrier. All NBLK CTAs are co-resident (1 CTA/SM,
// single wave), so this cannot deadlock. Leader resets count BEFORE the
// gen release, so there is no reset race with early arrivals at the next
// barrier. State after the kernel: count==0, gen monotonically grown —
// consistent for graph replays (comparison is relative).
__device__ __forceinline__ void grid_barrier() {
    __syncthreads();
    if (threadIdx.x == 0) {
        __threadfence();
        unsigned int gen = *(volatile unsigned int*)&g_gen;
        unsigned int c = atomicAdd(&g_count, 1u);
        if (c == NBLK - 1u) {
            atomicExch(&g_count, 0u);
            __threadfence();
            atomicAdd(&g_gen, 1u);        // release
        } else {
            while (*(volatile unsigned int*)&g_gen == gen) { __nanosleep(32); }
        }
        __threadfence();
    }
    __syncthreads();
}

extern "C" __global__ void __launch_bounds__(NTHR, 1)
lstm_persistent_kernel(const int*   __restrict__ inputs,   // [NB, SEQT]
                       const float* __restrict__ Wx,       // [NCHARS, ZC]
                       const float* __restrict__ Wh,       // [UNITS, ZC]
                       const float* __restrict__ bias,     // [ZC]
                       const float* __restrict__ Wd,       // [UNITS, NCHARS]
                       const float* __restrict__ bd,       // [NCHARS]
                       float*       __restrict__ out)      // [NB, NCHARS]
{
    extern __shared__ char smem[];
    float* w_s    = (float*)(smem + SMEM_W_OFF);    // [256][128] : w_s[k*128+c]
    float* h_s    = (float*)(smem + SMEM_H_OFF);    // [64][256]  : h_s[r*256+k]
    float* z_s    = h_s;                            // overlay after GEMM: [64][128]
    float* bias_s = (float*)(smem + SMEM_BIAS_OFF); // [128]
    float* hrow_s = (float*)(smem + SMEM_HROW_OFF); // [8][256] (final stage)

    const int tid = threadIdx.x;
    const int bt  = blockIdx.x & (NBT - 1);   // batch tile 0..15
    const int ht  = blockIdx.x >> 4;          // hidden tile 0..7
    const int b0  = bt * BM;

    // --- One-time: stage Wh slice + bias slice into smem ---
    // local col c -> global col: gate(c>>5)*256 + ht*32 + (c&31)
    for (int idx = tid; idx < W_S_ELEMS; idx += NTHR) {
        int k = idx >> 7;
        int c = idx & 127;
        int gcol = ((c >> 5) << 8) + ht * HN + (c & 31);
        w_s[idx] = Wh[k * ZC + gcol];
    }
    if (tid < BC) {
        int gcol = ((tid >> 5) << 8) + ht * HN + (tid & 31);
        bias_s[tid] = bias[gcol];
    }

    // Persistent cell state: 8 (b,u) pairs per thread.
    // pair j: u = tid&31, b = (tid>>5) + 8*j
    float creg[8];
#pragma unroll
    for (int j = 0; j < 8; j++) creg[j] = 0.0f;

    const int tr = tid >> 5;   // warp id 0..7  -> GEMM rows tr*8 .. tr*8+7
    const int tc = tid & 31;   // lane          -> GEMM cols tc*4 .. tc*4+3
    const int u  = tid & 31;   // gate-phase unit index

    __syncthreads();

    for (int t = 0; t < SEQT; t++) {
        const int cur = t & 1;
        const int nxt = cur ^ 1;

        // ---- Prefetch this step's chars + Wx gather (overlaps the GEMM) ----
        int ch[8];
#pragma unroll
        for (int j = 0; j < 8; j++) {
            int b = (tid >> 5) + 8 * j;
            ch[j] = __ldg(&inputs[(b0 + b) * SEQT + t]);
        }
        float xv0[8], xv1[8], xv2[8], xv3[8];
#pragma unroll
        for (int j = 0; j < 8; j++) {
            const float* wxr = Wx + ch[j] * ZC + ht * HN + u;
            xv0[j] = __ldg(wxr);
            xv1[j] = __ldg(wxr + 256);
            xv2[j] = __ldg(wxr + 512);
            xv3[j] = __ldg(wxr + 768);
        }

        float acc[8][4];
#pragma unroll
        for (int i = 0; i < 8; i++) {
            acc[i][0] = 0.f; acc[i][1] = 0.f; acc[i][2] = 0.f; acc[i][3] = 0.f;
        }

        if (t > 0) {
            // Load h tile [64][256] (coalesced global -> conflict-free smem)
            for (int idx = tid; idx < BM * UNITS_; idx += NTHR) {
                int r = idx >> 8;
                int uu = idx & 255;
                h_s[idx] = __ldg(&g_h[cur][(b0 + r) * UNITS_ + uu]);
            }
            __syncthreads();

            // GEMM: z[64][128] = h[64][256] * w[256][128]
            // w loads: LDS.128, 512B/warp contiguous -> conflict-free.
            // h loads: whole-warp broadcast of one float4.
            const float4* w4 = (const float4*)w_s;   // [256][32]
            const float4* h4 = (const float4*)h_s;   // [64][64]
#pragma unroll 2
            for (int k = 0; k < 256; k += 4) {
                float4 w0 = w4[(k + 0) * 32 + tc];
                float4 w1 = w4[(k + 1) * 32 + tc];
                float4 w2 = w4[(k + 2) * 32 + tc];
                float4 w3 = w4[(k + 3) * 32 + tc];
#pragma unroll
                for (int i = 0; i < 8; i++) {
                    float4 hv = h4[(tr * 8 + i) * 64 + (k >> 2)];
                    acc[i][0] = fmaf(hv.x, w0.x, acc[i][0]);
                    acc[i][0] = fmaf(hv.y, w1.x, acc[i][0]);
                    acc[i][0] = fmaf(hv.z, w2.x, acc[i][0]);
                    acc[i][0] = fmaf(hv.w, w3.x, acc[i][0]);
                    acc[i][1] = fmaf(hv.x, w0.y, acc[i][1]);
                    acc[i][1] = fmaf(hv.y, w1.y, acc[i][1]);
                    acc[i][1] = fmaf(hv.z, w2.y, acc[i][1]);
                    acc[i][1] = fmaf(hv.w, w3.y, acc[i][1]);
                    acc[i][2] = fmaf(hv.x, w0.z, acc[i][2]);
                    acc[i][2] = fmaf(hv.y, w1.z, acc[i][2]);
                    acc[i][2] = fmaf(hv.z, w2.z, acc[i][2]);
                    acc[i][2] = fmaf(hv.w, w3.z, acc[i][2]);
                    acc[i][3] = fmaf(hv.x, w0.w, acc[i][3]);
                    acc[i][3] = fmaf(hv.y, w1.w, acc[i][3]);
                    acc[i][3] = fmaf(hv.z, w2.w, acc[i][3]);
                    acc[i][3] = fmaf(hv.w, w3.w, acc[i][3]);
                }
            }
            __syncthreads();   // all warps done reading h_s before z_s overlay
        }

        // Stage z tile in smem (overlay of h_s)
        float4* z4 = (float4*)z_s;
#pragma unroll
        for (int i = 0; i < 8; i++)
            z4[(tr * 8 + i) * 32 + tc] = make_float4(acc[i][0], acc[i][1], acc[i][2], acc[i][3]);
        __syncthreads();

        // ---- Gate phase ----
#pragma unroll
        for (int j = 0; j < 8; j++) {
            int b = (tid >> 5) + 8 * j;
            float zi = z_s[b * BC +      u] + xv0[j] + bias_s[u];
            float zf = z_s[b * BC + 32 + u] + xv1[j] + bias_s[32 + u];
            float zg = z_s[b * BC + 64 + u] + xv2[j] + bias_s[64 + u];
            float zo = z_s[b * BC + 96 + u] + xv3[j] + bias_s[96 + u];
            float ig = fast_sigmoid(zi);
            float fg = fast_sigmoid(zf);
            float og = fast_sigmoid(zo);
            float gg = fast_tanh(zg);
            float c  = fmaf(fg, creg[j], ig * gg);
            creg[j] = c;
            float h  = og * fast_tanh(c);
            g_h[nxt][(b0 + b) * UNITS_ + ht * HN + u] = h;
        }

        grid_barrier();  // h(t+1) fully published before next step
    }

    // ---- Final stage: logits = h_final @ Wd + bd ; softmax ----
    // Each block handles 8 batch rows: blockIdx.x*8 .. +7
    const float* hfin = g_h[SEQT & 1] ? g_h[0] : g_h[0];  // SEQT even -> buffer 0
    const int rowbase = blockIdx.x * 8;

    for (int idx = tid; idx < UNITS_ * NCHARS; idx += NTHR)
        w_s[idx] = Wd[idx];                                   // reuse smem for Wd
    for (int idx = tid; idx < 8 * UNITS_; idx += NTHR) {
        int r = idx >> 8;
        int uu = idx & 255;
        hrow_s[idx] = hfin[(rowbase + r) * UNITS_ + uu];
    }
    __syncthreads();

    float* lg = h_s;   // [8][128] logits staging
    {
        int n  = tid & 127;
        int rr = tid >> 7;    // 0..1
#pragma unroll
        for (int q = 0; q < 4; q++) {
            int row = q * 2 + rr;
            float a = bd[n];
#pragma unroll 8
            for (int uu = 0; uu < UNITS_; uu++)
                a = fmaf(hrow_s[row * UNITS_ + uu], w_s[uu * NCHARS + n], a);
            lg[row * NCHARS + n] = a;
        }
    }
    __syncthreads();

    {   // softmax: one warp per row
        int w    = tid >> 5;
        int lane = tid & 31;
        float v[4];
        float mx = -3.402823466e38f;
#pragma unroll
        for (int q = 0; q < 4; q++) {
            v[q] = lg[w * NCHARS + lane + 32 * q];
            mx = fmaxf(mx, v[q]);
        }
#pragma unroll
        for (int s = 16; s > 0; s >>= 1) mx = fmaxf(mx, __shfl_xor_sync(0xFFFFFFFFu, mx, s));
        float sum = 0.f;
#pragma unroll
        for (int q = 0; q < 4; q++) { v[q] = __expf(v[q] - mx); sum += v[q]; }
#pragma unroll
        for (int s = 16; s > 0; s >>= 1) sum += __shfl_xor_sync(0xFFFFFFFFu, sum, s);
        float inv = 1.0f / sum;
        int bg = rowbase + w;
#pragma unroll
        for (int q = 0; q < 4; q++)
            out[bg * NCHARS + lane + 32 * q] = v[q] * inv;
    }
}

extern "C" void kernel_launch(void* const* d_in, const int* in_sizes, int n_in,
                              void* d_out, int out_size) {
    const int*   inputs = (const int*)  d_in[0];
    const float* Wx     = (const float*)d_in[1];
    const float* Wh     = (const float*)d_in[2];
    const float* b      = (const float*)d_in[3];
    const float* Wd     = (const float*)d_in[4];
    const float* bd     = (const float*)d_in[5];
    float* out = (float*)d_out;

    cudaFuncSetAttribute(lstm_persistent_kernel,
                         cudaFuncAttributeMaxDynamicSharedMemorySize, SMEM_TOTAL);

    lstm_persistent_kernel<<<NBLK, NTHR, SMEM_TOTAL>>>(inputs, Wx, Wh, b, Wd, bd, out);
}

// round 7
// speedup vs baseline: 2.0928x; 2.0928x over previous
#include <cuda_runtime.h>
#include <cuda_bf16.h>
#include <cstdint>

// Problem constants
#define NB      1024
#define SEQT    512
#define UNITS_  256
#define NCHARS  128
#define ZC      1024      // 4*UNITS

// Tiling: 128 blocks = 16 batch-tiles x 8 hidden-tiles
#define BM      64        // batch rows per block (GEMM M)
#define HN      32        // hidden units per block
#define BC      128       // z cols per block (GEMM N)
#define NBT     16
#define NHT     8
#define NBLK    128
#define NTHR    256

#define KDIM    256       // GEMM K
#define KP      264       // padded row length in bf16 elems (256 + 8)
#define KPB     528       // padded row bytes
#define ZP      132       // z row stride (floats)

// Shared memory layout (bytes)
#define OFF_WHI   0                         // Whi: [128 n][264 k] bf16 = 67584
#define OFF_WLO   67584                     // Wlo: 67584
#define OFF_AHI   135168                    // Ahi: [64 r][264 k] bf16 = 33792  (z overlays)
#define OFF_ALO   168960                    // Alo: 33792
#define OFF_Z     OFF_AHI                   // z: [64][132] fp32 = 33792 (overlay)
#define OFF_BIAS  202752                    // 128 floats
#define SMEM_TOTAL 203776

// Device-global scratch (zero-init at load)
__device__ unsigned int g_hx[2][NB * UNITS_];   // packed (bf16 hi | bf16 lo<<16)
__device__ unsigned int g_count, g_gen;

__device__ __forceinline__ float fast_sigmoid(float x) {
    return __fdividef(1.0f, 1.0f + __expf(-x));
}
__device__ __forceinline__ float fast_tanh(float x) {
    float e = __expf(2.0f * x);
    return 1.0f - __fdividef(2.0f, e + 1.0f);
}

// m16n8k16 row.col bf16 -> fp32 accumulate (baseline PTX, legal on plain sm_103)
__device__ __forceinline__ void mma16816(float& c0, float& c1, float& c2, float& c3,
                                         uint32_t a0, uint32_t a1, uint32_t a2, uint32_t a3,
                                         uint32_t b0, uint32_t b1) {
    asm volatile(
        "mma.sync.aligned.m16n8k16.row.col.f32.bf16.bf16.f32 "
        "{%0,%1,%2,%3}, {%4,%5,%6,%7}, {%8,%9}, {%0,%1,%2,%3};"
        : "+f"(c0), "+f"(c1), "+f"(c2), "+f"(c3)
        : "r"(a0), "r"(a1), "r"(a2), "r"(a3), "r"(b0), "r"(b1));
}

// Sense-reversing grid barrier; all NBLK CTAs co-resident (1 CTA/SM, single wave)
__device__ __forceinline__ void grid_barrier() {
    __syncthreads();
    if (threadIdx.x == 0) {
        __threadfence();
        unsigned int gen = *(volatile unsigned int*)&g_gen;
        unsigned int c = atomicAdd(&g_count, 1u);
        if (c == NBLK - 1u) {
            atomicExch(&g_count, 0u);
            __threadfence();
            atomicAdd(&g_gen, 1u);
        } else {
            while (*(volatile unsigned int*)&g_gen == gen) { __nanosleep(32); }
        }
        __threadfence();
    }
    __syncthreads();
}

extern "C" __global__ void __launch_bounds__(NTHR, 1)
lstm_hmma_kernel(const int*   __restrict__ inputs,   // [NB, SEQT]
                 const float* __restrict__ Wx,       // [NCHARS, ZC]
                 const float* __restrict__ Wh,       // [UNITS, ZC]
                 const float* __restrict__ bias,     // [ZC]
                 const float* __restrict__ Wd,       // [UNITS, NCHARS]
                 const float* __restrict__ bd,       // [NCHARS]
                 float*       __restrict__ out)      // [NB, NCHARS]
{
    extern __shared__ char smem[];
    float* bias_s = (float*)(smem + OFF_BIAS);
    float* z_s    = (float*)(smem + OFF_Z);

    const int tid  = threadIdx.x;
    const int wid  = tid >> 5;
    const int lane = tid & 31;
    const int bt   = blockIdx.x & (NBT - 1);
    const int ht   = blockIdx.x >> 4;
    const int b0   = bt * BM;

    // ---- One-time: Wh slice -> bf16 hi/lo, stored [n][k] (k padded to 264) ----
    // local col n -> global col: gate(n>>5)*256 + ht*32 + (n&31)
    for (int idx = tid; idx < BC * KDIM; idx += NTHR) {
        int n = idx >> 8;          // 0..127
        int k = idx & 255;         // 0..255
        int gcol = ((n >> 5) << 8) + ht * HN + (n & 31);
        float w = Wh[k * ZC + gcol];
        __nv_bfloat16 hi = __float2bfloat16(w);
        __nv_bfloat16 lo = __float2bfloat16(w - __bfloat162float(hi));
        *(__nv_bfloat16*)(smem + OFF_WHI + n * KPB + k * 2) = hi;
        *(__nv_bfloat16*)(smem + OFF_WLO + n * KPB + k * 2) = lo;
    }
    if (tid < BC) {
        int gcol = ((tid >> 5) << 8) + ht * HN + (tid & 31);
        bias_s[tid] = bias[gcol];
    }
    // zero z region (t=0 gate phase reads zeros)
    for (int idx = tid; idx < BM * ZP; idx += NTHR) z_s[idx] = 0.0f;

    float creg[8];
#pragma unroll
    for (int j = 0; j < 8; j++) creg[j] = 0.0f;

    // MMA warp mapping: wm = row tile (16 rows), wn = col half (64 cols)
    const int g  = lane >> 2;      // 0..7
    const int tg = lane & 3;       // 0..3
    const int wm = wid & 3;
    const int wn = wid >> 2;
    const uint32_t aoff = (uint32_t)((16 * wm + g) * KPB + 4 * tg);
    const uint32_t boff = (uint32_t)((64 * wn + g) * KPB + 4 * tg);

    // Gate-phase mapping
    const int u = lane;            // unit 0..31 (z col low 5 bits)

    __syncthreads();

    for (int t = 0; t < SEQT; t++) {
        const int cur = t & 1;
        const int nxt = cur ^ 1;

        // ---- Prefetch chars + Wx gather (overlaps staging + MMA) ----
        int ch[8];
#pragma unroll
        for (int j = 0; j < 8; j++)
            ch[j] = __ldg(&inputs[(b0 + wid + 8 * j) * SEQT + t]);
        float xv0[8], xv1[8], xv2[8], xv3[8];
#pragma unroll
        for (int j = 0; j < 8; j++) {
            const float* wxr = Wx + ch[j] * ZC + ht * HN + u;
            xv0[j] = __ldg(wxr);
            xv1[j] = __ldg(wxr + 256);
            xv2[j] = __ldg(wxr + 512);
            xv3[j] = __ldg(wxr + 768);
        }

        if (t > 0) {
            // ---- Stage A: split packed h into bf16 hi/lo tiles [64][264] ----
            for (int gidx = tid; gidx < BM * 64; gidx += NTHR) {
                int r  = gidx >> 6;
                int k0 = (gidx & 63) << 2;
                uint4 p = *(const uint4*)&g_hx[cur][(b0 + r) * UNITS_ + k0];
                uint32_t hi01 = __byte_perm(p.x, p.y, 0x5410);
                uint32_t hi23 = __byte_perm(p.z, p.w, 0x5410);
                uint32_t lo01 = __byte_perm(p.x, p.y, 0x7632);
                uint32_t lo23 = __byte_perm(p.z, p.w, 0x7632);
                uint32_t byte = (uint32_t)(r * KPB + k0 * 2);
                *(uint2*)(smem + OFF_AHI + byte) = make_uint2(hi01, hi23);
                *(uint2*)(smem + OFF_ALO + byte) = make_uint2(lo01, lo23);
            }
            __syncthreads();

            // ---- MMA phase: C[64][128] = Ahi*Whi + Alo*Whi + Ahi*Wlo ----
            float acc[8][4];
#pragma unroll
            for (int j = 0; j < 8; j++) {
                acc[j][0] = 0.f; acc[j][1] = 0.f; acc[j][2] = 0.f; acc[j][3] = 0.f;
            }

#pragma unroll 2
            for (int kc = 0; kc < 16; kc++) {
                const uint32_t kb = (uint32_t)(kc * 32);   // 16 bf16 = 32 bytes
                uint32_t ah0 = *(const uint32_t*)(smem + OFF_AHI + aoff + kb);
                uint32_t ah1 = *(const uint32_t*)(smem + OFF_AHI + aoff + kb + 8 * KPB);
                uint32_t ah2 = *(const uint32_t*)(smem + OFF_AHI + aoff + kb + 16);
                uint32_t ah3 = *(const uint32_t*)(smem + OFF_AHI + aoff + kb + 8 * KPB + 16);
                uint32_t al0 = *(const uint32_t*)(smem + OFF_ALO + aoff + kb);
                uint32_t al1 = *(const uint32_t*)(smem + OFF_ALO + aoff + kb + 8 * KPB);
                uint32_t al2 = *(const uint32_t*)(smem + OFF_ALO + aoff + kb + 16);
                uint32_t al3 = *(const uint32_t*)(smem + OFF_ALO + aoff + kb + 8 * KPB + 16);

                uint32_t bh[8][2], bl[8][2];
#pragma unroll
                for (int j = 0; j < 8; j++) {
                    uint32_t bo = boff + (uint32_t)(j * 8 * KPB) + kb;
                    bh[j][0] = *(const uint32_t*)(smem + OFF_WHI + bo);
                    bh[j][1] = *(const uint32_t*)(smem + OFF_WHI + bo + 16);
                    bl[j][0] = *(const uint32_t*)(smem + OFF_WLO + bo);
                    bl[j][1] = *(const uint32_t*)(smem + OFF_WLO + bo + 16);
                }
#pragma unroll
                for (int j = 0; j < 8; j++)
                    mma16816(acc[j][0], acc[j][1], acc[j][2], acc[j][3],
                             ah0, ah1, ah2, ah3, bh[j][0], bh[j][1]);
#pragma unroll
                for (int j = 0; j < 8; j++)
                    mma16816(acc[j][0], acc[j][1], acc[j][2], acc[j][3],
                             al0, al1, al2, al3, bh[j][0], bh[j][1]);
#pragma unroll
                for (int j = 0; j < 8; j++)
                    mma16816(acc[j][0], acc[j][1], acc[j][2], acc[j][3],
                             ah0, ah1, ah2, ah3, bl[j][0], bl[j][1]);
            }
            __syncthreads();   // all A reads done before z overlays A_hi

            // ---- Store z tile from accumulators ----
#pragma unroll
            for (int j = 0; j < 8; j++) {
                int col  = 64 * wn + 8 * j + 2 * tg;
                int row0 = 16 * wm + g;
                *(float2*)(z_s + row0 * ZP + col)       = make_float2(acc[j][0], acc[j][1]);
                *(float2*)(z_s + (row0 + 8) * ZP + col) = make_float2(acc[j][2], acc[j][3]);
            }
            __syncthreads();
        }

        // ---- Gate phase: thread handles (b = wid + 8j, unit u) ----
#pragma unroll
        for (int j = 0; j < 8; j++) {
            int b = wid + 8 * j;
            float zi = z_s[b * ZP +      u] + xv0[j] + bias_s[u];
            float zf = z_s[b * ZP + 32 + u] + xv1[j] + bias_s[32 + u];
            float zg = z_s[b * ZP + 64 + u] + xv2[j] + bias_s[64 + u];
            float zo = z_s[b * ZP + 96 + u] + xv3[j] + bias_s[96 + u];
            float ig = fast_sigmoid(zi);
            float fg = fast_sigmoid(zf);
            float og = fast_sigmoid(zo);
            float gg = fast_tanh(zg);
            float c  = fmaf(fg, creg[j], ig * gg);
            creg[j] = c;
            float h  = og * fast_tanh(c);
            __nv_bfloat16 hh = __float2bfloat16(h);
            __nv_bfloat16 hl = __float2bfloat16(h - __bfloat162float(hh));
            unsigned int word = (unsigned int)__bfloat16_as_ushort(hh) |
                                ((unsigned int)__bfloat16_as_ushort(hl) << 16);
            g_hx[nxt][(b0 + b) * UNITS_ + ht * HN + u] = word;
        }

        grid_barrier();
    }

    // ---- Final stage: logits = h_final @ Wd + bd ; softmax ----
    // Final h is in g_hx[0] (t=511: cur=1, nxt=0). Each block: 8 batch rows.
    const int rowbase = blockIdx.x * 8;
    float* wd_s   = (float*)(smem + OFF_WHI);   // [0,131072) for Wd
    float* hrow_s = (float*)(smem + OFF_ALO);   // 8x256 fp32
    float* lg     = (float*)(smem + OFF_AHI);   // 8x128 logits

    __syncthreads();
    for (int idx = tid; idx < UNITS_ * NCHARS; idx += NTHR)
        wd_s[idx] = Wd[idx];
    for (int idx = tid; idx < 8 * UNITS_; idx += NTHR) {
        int r  = idx >> 8;
        int uu = idx & 255;
        unsigned int word = g_hx[0][(rowbase + r) * UNITS_ + uu];
        float h = __bfloat162float(__ushort_as_bfloat16((unsigned short)(word & 0xFFFF))) +
                  __bfloat162float(__ushort_as_bfloat16((unsigned short)(word >> 16)));
        hrow_s[idx] = h;
    }
    __syncthreads();

    {
        int n  = tid & 127;
        int rr = tid >> 7;
#pragma unroll
        for (int q = 0; q < 4; q++) {
            int row = q * 2 + rr;
            float a = bd[n];
#pragma unroll 8
            for (int uu = 0; uu < UNITS_; uu++)
                a = fmaf(hrow_s[row * UNITS_ + uu], wd_s[uu * NCHARS + n], a);
            lg[row * NCHARS + n] = a;
        }
    }
    __syncthreads();

    {   // softmax: one warp per row
        int w = tid >> 5;
        float v[4];
        float mx = -3.402823466e38f;
#pragma unroll
        for (int q = 0; q < 4; q++) {
            v[q] = lg[w * NCHARS + lane + 32 * q];
            mx = fmaxf(mx, v[q]);
        }
#pragma unroll
        for (int s = 16; s > 0; s >>= 1) mx = fmaxf(mx, __shfl_xor_sync(0xFFFFFFFFu, mx, s));
        float sum = 0.f;
#pragma unroll
        for (int q = 0; q < 4; q++) { v[q] = __expf(v[q] - mx); sum += v[q]; }
#pragma unroll
        for (int s = 16; s > 0; s >>= 1) sum += __shfl_xor_sync(0xFFFFFFFFu, sum, s);
        float inv = 1.0f / sum;
        int bg = rowbase + w;
#pragma unroll
        for (int q = 0; q < 4; q++)
            out[bg * NCHARS + lane + 32 * q] = v[q] * inv;
    }
}

extern "C" void kernel_launch(void* const* d_in, const int* in_sizes, int n_in,
                              void* d_out, int out_size) {
    const int*   inputs = (const int*)  d_in[0];
    const float* Wx     = (const float*)d_in[1];
    const float* Wh     = (const float*)d_in[2];
    const float* b      = (const float*)d_in[3];
    const float* Wd     = (const float*)d_in[4];
    const float* bd     = (const float*)d_in[5];
    float* out = (float*)d_out;

    cudaFuncSetAttribute(lstm_hmma_kernel,
                         cudaFuncAttributeMaxDynamicSharedMemorySize, SMEM_TOTAL);

    lstm_hmma_kernel<<<NBLK, NTHR, SMEM_TOTAL>>>(inputs, Wx, Wh, b, Wd, bd, out);
}